// round 15
// baseline (speedup 1.0000x reference)
#include <cuda_runtime.h>
#include <cuda_fp16.h>
#include <cstdint>
#include <math.h>

// ---------------- problem constants ----------------
#define BATCH   64
#define NPATCH  196
#define NVIS    49
#define ENC     768
#define DEC     512
#define FFN     2048
#define OUTD    3072      // 16*16*12
#define NLAYERS 8
#define NHEADS  16
#define HD      32
#define IMG     224
#define CIN     12
#define PS      16

#define TOK_FULL (BATCH*NPATCH)   // 12544
#define TOK_VIS  (BATCH*NVIS)     // 3136

// transposed fp16 weight offsets (elements)
#define OFF_WP   0
#define OFF_WE2D (OFF_WP   + OUTD*ENC)
#define OFF_WQKV (OFF_WE2D + ENC*DEC)
#define OFF_WO   (OFF_WQKV + NLAYERS*DEC*3*DEC)
#define OFF_W1   (OFF_WO   + NLAYERS*DEC*DEC)
#define OFF_W2   (OFF_W1   + NLAYERS*DEC*FFN)
#define OFF_WR   (OFF_W2   + NLAYERS*FFN*DEC)
#define WTS_TOTAL (OFF_WR  + DEC*OUTD)

// ---------------- scratch (device globals; no allocation) ----------------
__device__ __half g_vp16 [TOK_VIS * OUTD];
__device__ float  g_enc  [TOK_VIS * ENC];
__device__ __half g_enc16[TOK_VIS * ENC];
__device__ float  g_dec  [TOK_VIS * DEC];
__device__ float  g_h    [TOK_FULL * DEC];
__device__ __half g_h16  [TOK_FULL * DEC];
__device__ float  g_qkv  [TOK_FULL * 3*DEC];
__device__ __half g_attn16[TOK_FULL * DEC];
__device__ __half g_ffn16[TOK_FULL * FFN];
__device__ float  g_tmp  [TOK_FULL * DEC];
__device__ __half g_wt16 [WTS_TOTAL];        // transposed [N][K] fp16 weights
__device__ int    g_vis_idx[TOK_VIS];
__device__ int    g_slot[TOK_FULL];
__device__ int    g_mode;

// ---------------- packed f32x2 helpers (Blackwell) ----------------
__device__ __forceinline__ uint64_t pack2(float lo, float hi) {
    uint64_t r; asm("mov.b64 %0, {%1, %2};" : "=l"(r) : "f"(lo), "f"(hi)); return r;
}
__device__ __forceinline__ void unpack2(float& lo, float& hi, uint64_t v) {
    asm("mov.b64 {%0, %1}, %2;" : "=f"(lo), "=f"(hi) : "l"(v));
}
#define FMA2(d, a, b) \
    asm("fma.rn.f32x2 %0, %1, %2, %0;" : "+l"(d) : "l"(a), "l"(b))

// ---------------- mask dtype detection ----------------
__global__ void detect_mask_mode(const void* mask) {
    if (threadIdx.x != 0 || blockIdx.x != 0) return;
    {
        const int* p = (const int*)mask;
        bool ok = true; int s = 0;
        for (int i = 0; i < NPATCH; i++) { int v = p[i]; if (v != 0 && v != 1) { ok = false; break; } s += v; }
        if (ok && s == NPATCH - NVIS) { g_mode = 0; return; }
    }
    {
        const unsigned char* p = (const unsigned char*)mask;
        int s = 0;
        for (int i = 0; i < NPATCH; i++) s += (p[i] != 0);
        if (s == NPATCH - NVIS) { g_mode = 1; return; }
    }
    g_mode = 2;
}

__global__ void build_indices(const void* mask) {
    int b = blockIdx.x;
    if (threadIdx.x != 0) return;
    int mode = g_mode;
    const int*           pi = (const int*)mask;
    const unsigned char* pb = (const unsigned char*)mask;
    const float*         pf = (const float*)mask;
    int cnt = 0;
    for (int n = 0; n < NPATCH; n++) {
        int idx = b * NPATCH + n;
        bool m;
        if (mode == 0)      m = (pi[idx] != 0);
        else if (mode == 1) m = (pb[idx] != 0);
        else                m = (pf[idx] != 0.0f);
        if (!m) {
            if (cnt < NVIS) g_vis_idx[b * NVIS + cnt] = n;
            g_slot[idx] = cnt;
            cnt++;
        } else {
            g_slot[idx] = -1;
        }
    }
}

// ---------------- gather visible patches (fp16: A of patch GEMM) ----------
__global__ void gather_patches(const float* __restrict__ x) {
    int idx = blockIdx.x * blockDim.x + threadIdx.x;
    if (idx >= TOK_VIS * OUTD) return;
    int f  = idx % OUTD;
    int bv = idx / OUTD;
    int b  = bv / NVIS;
    int n  = g_vis_idx[bv];
    int c  = f >> 8;
    int r  = f & 255;
    int ph = r >> 4, pw = r & 15;
    int hp = n / 14, wp = n % 14;
    g_vp16[idx] = __float2half(x[(((size_t)(b * CIN + c)) * IMG + hp * PS + ph) * IMG + wp * PS + pw]);
}

// ---------------- weight transpose + fp16 convert: W[K][N] -> WT[N][K] -----
__global__ void transpose_h(const float* __restrict__ src, __half* __restrict__ dst,
                            int K, int N, long long sstride, long long dstride) {
    src += (long long)blockIdx.z * sstride;
    dst += (long long)blockIdx.z * dstride;
    __shared__ float t[32][33];
    int n0 = blockIdx.x * 32, k0 = blockIdx.y * 32;
    #pragma unroll
    for (int i = threadIdx.y; i < 32; i += 8)
        t[i][threadIdx.x] = src[(size_t)(k0 + i) * N + n0 + threadIdx.x];
    __syncthreads();
    #pragma unroll
    for (int i = threadIdx.y; i < 32; i += 8)
        dst[(size_t)(n0 + i) * K + k0 + threadIdx.x] = __float2half(t[threadIdx.x][i]);
}

// ---------------- fast exact GELU (A&S 7.1.26 erf, |eps| <= 1.5e-7) --------
__device__ __forceinline__ float gelu_exact(float x) {
    float az = fabsf(x) * 0.70710678118654752f;
    float den = fmaf(0.3275911f, az, 1.0f);
    float t;
    asm("rcp.approx.f32 %0, %1;" : "=f"(t) : "f"(den));
    float p = fmaf(1.061405429f, t, -1.453152027f);
    p = fmaf(p, t, 1.421413741f);
    p = fmaf(p, t, -0.284496736f);
    p = fmaf(p, t, 0.254829592f);
    p = p * t;
    float e = __expf(-az * az);
    float q = 0.5f * x * p * e;
    return (x >= 0.f) ? (x - q) : q;
}

// ---------------- shared mma helpers ----------------
__device__ __forceinline__ void cp_async16(uint32_t dst, const void* src, int srcBytes) {
    asm volatile("cp.async.ca.shared.global [%0], [%1], 16, %2;\n"
                 :: "r"(dst), "l"(src), "r"(srcBytes));
}
__device__ __forceinline__ void cp_commit() {
    asm volatile("cp.async.commit_group;\n");
}
template<int N_>
__device__ __forceinline__ void cp_wait() {
    asm volatile("cp.async.wait_group %0;\n" :: "n"(N_));
}
__device__ __forceinline__ void ldsm_x4(uint32_t& r0, uint32_t& r1, uint32_t& r2, uint32_t& r3,
                                        uint32_t saddr) {
    asm volatile("ldmatrix.sync.aligned.m8n8.x4.shared.b16 {%0,%1,%2,%3}, [%4];\n"
                 : "=r"(r0), "=r"(r1), "=r"(r2), "=r"(r3) : "r"(saddr));
}
__device__ __forceinline__ void mma_f16(float c[4], const uint32_t a[4], const uint32_t b[2]) {
    asm volatile(
        "mma.sync.aligned.m16n8k16.row.col.f32.f16.f16.f32 "
        "{%0,%1,%2,%3}, {%4,%5,%6,%7}, {%8,%9}, {%0,%1,%2,%3};\n"
        : "+f"(c[0]), "+f"(c[1]), "+f"(c[2]), "+f"(c[3])
        : "r"(a[0]), "r"(a[1]), "r"(a[2]), "r"(a[3]), "r"(b[0]), "r"(b[1]));
}

// =====================================================================
// fp16 GEMM (R10 winner): 128x128 block, BK=32, warp tile 64x32,
// ldmatrix.x4 fragment loads, double-buffered cp.async, 2 CTAs/SM.
// N%128==0, K%32==0. M guarded.
// =====================================================================
#define RSW 20
#define TILE_W (128 * RSW)

template<int EPI, int OUT>   // EPI: 0=bias 1=+gelu 2=+residual ; OUT: 0=f32 1=f16 2=both
__global__ __launch_bounds__(256, 2)
void gemm_h(const __half* __restrict__ A, const __half* __restrict__ BT,
            const float* __restrict__ bias, const float* __restrict__ R,
            float* __restrict__ C, __half* __restrict__ C16,
            int M, int N, int K)
{
    __shared__ uint32_t As[2][TILE_W];
    __shared__ uint32_t Bs[2][TILE_W];

    const int tid  = threadIdx.x;
    const int wid  = tid >> 5;
    const int lane = tid & 31;
    const int g    = lane >> 2;
    const int tig  = lane & 3;
    const int wm   = wid & 1;
    const int wn   = wid >> 1;
    const int rowBase = blockIdx.y * 128;
    const int colBase = blockIdx.x * 128;

    float acc[4][4][4];
    #pragma unroll
    for (int mt = 0; mt < 4; mt++)
        #pragma unroll
        for (int nt = 0; nt < 4; nt++)
            #pragma unroll
            for (int r = 0; r < 4; r++) acc[mt][nt][r] = 0.f;

    const uint32_t sA = (uint32_t)__cvta_generic_to_shared(&As[0][0]);
    const uint32_t sB = (uint32_t)__cvta_generic_to_shared(&Bs[0][0]);

    const int ldRow = tid >> 2;
    const int ldC   = tid & 3;
    const int aRow0 = rowBase + ldRow;
    const int aRow1 = rowBase + ldRow + 64;
    const int aOk0  = (aRow0 < M) ? 16 : 0;
    const int aOk1  = (aRow1 < M) ? 16 : 0;
    const int aRc0  = (aRow0 < M) ? aRow0 : 0;
    const int aRc1  = (aRow1 < M) ? aRow1 : 0;
    const int bRow0 = colBase + ldRow;
    const int bRow1 = colBase + ldRow + 64;
    const uint32_t dOff0 = (uint32_t)((ldRow * RSW + ldC * 4) * 4);
    const uint32_t dOff1 = (uint32_t)(((ldRow + 64) * RSW + ldC * 4) * 4);

    uint32_t aAddr[4];
    #pragma unroll
    for (int mt = 0; mt < 4; mt++) {
        int row = wm * 64 + mt * 16 + (lane & 15);
        aAddr[mt] = sA + (uint32_t)((row * RSW + (lane >> 4) * 4) * 4);
    }
    uint32_t bAddr[2];
    #pragma unroll
    for (int p = 0; p < 2; p++) {
        int row = wn * 32 + p * 16 + ((lane >> 4) & 1) * 8 + (lane & 7);
        bAddr[p] = sB + (uint32_t)((row * RSW + ((lane >> 3) & 1) * 4) * 4);
    }

    const int nIters = K >> 5;

    {
        cp_async16(sA + dOff0, A + (size_t)aRc0 * K + ldC * 8, aOk0);
        cp_async16(sA + dOff1, A + (size_t)aRc1 * K + ldC * 8, aOk1);
        cp_async16(sB + dOff0, BT + (size_t)bRow0 * K + ldC * 8, 16);
        cp_async16(sB + dOff1, BT + (size_t)bRow1 * K + ldC * 8, 16);
        cp_commit();
    }

    for (int it = 0; it < nIters; it++) {
        const int buf = it & 1;
        if (it + 1 < nIters) {
            const int nbuf = buf ^ 1;
            const int k0 = (it + 1) << 5;
            const uint32_t bufOff = (uint32_t)(nbuf * TILE_W * 4);
            cp_async16(sA + bufOff + dOff0, A + (size_t)aRc0 * K + k0 + ldC * 8, aOk0);
            cp_async16(sA + bufOff + dOff1, A + (size_t)aRc1 * K + k0 + ldC * 8, aOk1);
            cp_async16(sB + bufOff + dOff0, BT + (size_t)bRow0 * K + k0 + ldC * 8, 16);
            cp_async16(sB + bufOff + dOff1, BT + (size_t)bRow1 * K + k0 + ldC * 8, 16);
            cp_commit();
            cp_wait<1>();
        } else {
            cp_wait<0>();
        }
        __syncthreads();

        const uint32_t bufB = (uint32_t)(buf * TILE_W * 4);
        #pragma unroll
        for (int ks = 0; ks < 2; ks++) {
            const uint32_t ksB = (uint32_t)(ks * 32);
            uint32_t bfrag[4][2];
            #pragma unroll
            for (int p = 0; p < 2; p++) {
                ldsm_x4(bfrag[2 * p][0], bfrag[2 * p][1],
                        bfrag[2 * p + 1][0], bfrag[2 * p + 1][1],
                        bAddr[p] + bufB + ksB);
            }
            uint32_t afrag[4][4];
            #pragma unroll
            for (int mt = 0; mt < 4; mt++) {
                ldsm_x4(afrag[mt][0], afrag[mt][1], afrag[mt][2], afrag[mt][3],
                        aAddr[mt] + bufB + ksB);
            }
            #pragma unroll
            for (int mt = 0; mt < 4; mt++)
                #pragma unroll
                for (int nt = 0; nt < 4; nt++)
                    mma_f16(acc[mt][nt], afrag[mt], bfrag[nt]);
        }
        __syncthreads();
    }

    #pragma unroll
    for (int mt = 0; mt < 4; mt++) {
        int row0 = rowBase + wm * 64 + mt * 16 + g;
        #pragma unroll
        for (int nt = 0; nt < 4; nt++) {
            int col = colBase + wn * 32 + nt * 8 + tig * 2;
            float b0 = bias[col], b1 = bias[col + 1];
            #pragma unroll
            for (int half_ = 0; half_ < 2; half_++) {
                int row = row0 + half_ * 8;
                if (row >= M) continue;
                float v0 = acc[mt][nt][half_ * 2 + 0] + b0;
                float v1 = acc[mt][nt][half_ * 2 + 1] + b1;
                if (EPI == 1) { v0 = gelu_exact(v0); v1 = gelu_exact(v1); }
                if (EPI == 2) {
                    float2 rv = *(const float2*)(R + (size_t)row * N + col);
                    v0 += rv.x; v1 += rv.y;
                }
                if (OUT == 0 || OUT == 2) {
                    float2 o; o.x = v0; o.y = v1;
                    *(float2*)(C + (size_t)row * N + col) = o;
                }
                if (OUT == 1 || OUT == 2) {
                    *(__half2*)(C16 + (size_t)row * N + col) = __floats2half2_rn(v0, v1);
                }
            }
        }
    }
}

// ---------------- mask-token assembly + pos embed (dual write) ------------
__global__ void assemble(const float* __restrict__ mask_token,
                         const float* __restrict__ pos) {
    int idx = blockIdx.x * blockDim.x + threadIdx.x;
    if (idx >= TOK_FULL * DEC) return;
    int d  = idx & (DEC - 1);
    int bn = idx >> 9;
    int n  = bn % NPATCH;
    int b  = bn / NPATCH;
    int sl = g_slot[bn];
    float v = (sl < 0) ? mask_token[d] : g_dec[(size_t)(b * NVIS + sl) * DEC + d];
    v += pos[n * DEC + d];
    g_h[idx]   = v;
    g_h16[idx] = __float2half(v);
}

// ---------------- attention: packed f32x2 FMA, 2 keys per iteration -------
// Scores tiny (|d| <~ 1): softmax without max-subtraction is identical math.
// Processing key pairs (jn always even: 64/64/64/4) gives two independent
// score chains + pipelined exps; update ORDER (j then j+1) is identical to
// the sequential version, so results are bitwise unchanged.
__global__ __launch_bounds__(224)
void attn_kernel(const float* __restrict__ qkv, __half* __restrict__ out16) {
    const int S = NPATCH;
    int b = blockIdx.x >> 4;
    int h = blockIdx.x & 15;
    int tid = threadIdx.x;
    __shared__ float4 Kt4[64][8];
    __shared__ float4 Vt4[64][8];

    // q packed: 16 f32x2 pairs (32 floats)
    uint64_t q2[16];
    const float* qbase = qkv + (size_t)(b * S) * (3 * DEC) + h * HD;
    if (tid < S) {
        const float4* qp = (const float4*)(qbase + (size_t)tid * (3 * DEC));
        #pragma unroll
        for (int i = 0; i < 8; i++) {
            float4 qv = qp[i];
            q2[2 * i]     = pack2(qv.x, qv.y);
            q2[2 * i + 1] = pack2(qv.z, qv.w);
        }
    }
    // o accumulators packed: 16 f32x2 pairs (32 floats)
    uint64_t o2[16];
    #pragma unroll
    for (int i = 0; i < 16; i++) o2[i] = 0ull;
    float s = 0.f;
    const float scale = 0.17677669529663689f; // 1/sqrt(32)

    for (int j0 = 0; j0 < S; j0 += 64) {
        int jn = min(64, S - j0);
        for (int idx = tid; idx < jn * 8; idx += blockDim.x) {
            int jj = idx >> 3, kk = idx & 7;
            const float4* base = (const float4*)(qkv + (size_t)(b * S + j0 + jj) * (3 * DEC) + h * HD);
            Kt4[jj][kk] = base[DEC / 4 + kk];
            Vt4[jj][kk] = base[2 * DEC / 4 + kk];
        }
        __syncthreads();
        if (tid < S) {
            for (int jj = 0; jj < jn; jj += 2) {
                const ulonglong2* kt0 = (const ulonglong2*)(&Kt4[jj][0]);
                const ulonglong2* kt1 = (const ulonglong2*)(&Kt4[jj + 1][0]);
                uint64_t d0a = 0ull, d1a = 0ull;
                uint64_t d0b = 0ull, d1b = 0ull;
                #pragma unroll
                for (int i = 0; i < 8; i++) {
                    ulonglong2 kv0 = kt0[i];
                    ulonglong2 kv1 = kt1[i];
                    FMA2(d0a, q2[2 * i],     kv0.x);
                    FMA2(d0b, q2[2 * i],     kv1.x);
                    FMA2(d1a, q2[2 * i + 1], kv0.y);
                    FMA2(d1b, q2[2 * i + 1], kv1.y);
                }
                float a0, a1, a2, a3, b0, b1, b2, b3;
                unpack2(a0, a1, d0a); unpack2(a2, a3, d1a);
                unpack2(b0, b1, d0b); unpack2(b2, b3, d1b);
                float da = ((a0 + a2) + (a1 + a3)) * scale;
                float db = ((b0 + b2) + (b1 + b3)) * scale;
                float p0 = __expf(da);
                float p1 = __expf(db);
                s += p0;
                s += p1;
                uint64_t pp0 = pack2(p0, p0);
                uint64_t pp1 = pack2(p1, p1);
                const ulonglong2* vt0 = (const ulonglong2*)(&Vt4[jj][0]);
                const ulonglong2* vt1 = (const ulonglong2*)(&Vt4[jj + 1][0]);
                #pragma unroll
                for (int i = 0; i < 8; i++) {
                    ulonglong2 vv0 = vt0[i];
                    ulonglong2 vv1 = vt1[i];
                    FMA2(o2[2 * i],     pp0, vv0.x);
                    FMA2(o2[2 * i],     pp1, vv1.x);
                    FMA2(o2[2 * i + 1], pp0, vv0.y);
                    FMA2(o2[2 * i + 1], pp1, vv1.y);
                }
            }
        }
        __syncthreads();
    }
    if (tid < S) {
        float inv = 1.f / s;
        __half2* op = (__half2*)(out16 + (size_t)(b * S + tid) * DEC + h * HD);
        #pragma unroll
        for (int i = 0; i < 8; i++) {
            float x0, x1, x2, x3;
            unpack2(x0, x1, o2[2 * i]);
            unpack2(x2, x3, o2[2 * i + 1]);
            op[2 * i]     = __floats2half2_rn(x0 * inv, x1 * inv);
            op[2 * i + 1] = __floats2half2_rn(x2 * inv, x3 * inv);
        }
    }
}

// ---------------- layernorm: warp-per-row, 8 rows/CTA, shuffle-only -------
__global__ __launch_bounds__(256)
void ln_kernel(const float* __restrict__ X, const float* __restrict__ g,
               const float* __restrict__ bta,
               float* __restrict__ Y, __half* __restrict__ Y16) {
    int warp = threadIdx.x >> 5;
    int lane = threadIdx.x & 31;
    int row  = blockIdx.x * 8 + warp;

    const float4* x4 = (const float4*)(X + (size_t)row * DEC);
    const float4* g4 = (const float4*)g;
    const float4* b4 = (const float4*)bta;

    float4 v[4];
    float sum = 0.f, sq = 0.f;
    #pragma unroll
    for (int i = 0; i < 4; i++) {
        v[i] = x4[lane + 32 * i];
        sum += (v[i].x + v[i].y) + (v[i].z + v[i].w);
        sq  = fmaf(v[i].x, v[i].x, sq);
        sq  = fmaf(v[i].y, v[i].y, sq);
        sq  = fmaf(v[i].z, v[i].z, sq);
        sq  = fmaf(v[i].w, v[i].w, sq);
    }
    #pragma unroll
    for (int o = 16; o > 0; o >>= 1) {
        sum += __shfl_xor_sync(0xffffffffu, sum, o);
        sq  += __shfl_xor_sync(0xffffffffu, sq,  o);
    }
    float mean = sum * (1.f / DEC);
    float var  = sq * (1.f / DEC) - mean * mean;
    float r = rsqrtf(var + 1e-5f);

    float4*  y4  = (float4*)(Y + (size_t)row * DEC);
    __half2* y16 = (__half2*)(Y16 + (size_t)row * DEC);
    #pragma unroll
    for (int i = 0; i < 4; i++) {
        float4 gv = g4[lane + 32 * i];
        float4 bv = b4[lane + 32 * i];
        float4 o;
        o.x = (v[i].x - mean) * r * gv.x + bv.x;
        o.y = (v[i].y - mean) * r * gv.y + bv.y;
        o.z = (v[i].z - mean) * r * gv.z + bv.z;
        o.w = (v[i].w - mean) * r * gv.w + bv.w;
        y4[lane + 32 * i] = o;
        y16[(lane + 32 * i) * 2]     = __floats2half2_rn(o.x, o.y);
        y16[(lane + 32 * i) * 2 + 1] = __floats2half2_rn(o.z, o.w);
    }
}

// ---------------- host orchestration ----------------
static void launch_gemm(int epi, int outm,
                        const __half* A, const __half* BT, const float* bias,
                        const float* R, float* C, __half* C16,
                        int M, int N, int K) {
    dim3 grid(N / 128, (M + 127) / 128);
    #define GC(E, O) gemm_h<E, O><<<grid, 256>>>(A, BT, bias, R, C, C16, M, N, K)
    if (epi == 0) { if (outm == 0) GC(0,0); else if (outm == 1) GC(0,1); else GC(0,2); }
    else if (epi == 1) { if (outm == 0) GC(1,0); else if (outm == 1) GC(1,1); else GC(1,2); }
    else { if (outm == 0) GC(2,0); else if (outm == 1) GC(2,1); else GC(2,2); }
    #undef GC
}

static void launch_transpose(const float* src, __half* dst, int K, int N,
                             int layers, long long sstride, long long dstride) {
    dim3 grid(N / 32, K / 32, layers);
    transpose_h<<<grid, dim3(32, 8)>>>(src, dst, K, N, sstride, dstride);
}

extern "C" void kernel_launch(void* const* d_in, const int* in_sizes, int n_in,
                              void* d_out, int out_size) {
    const float* x          = (const float*)d_in[0];
    const void*  mask       = d_in[1];
    const float* Wp         = (const float*)d_in[3];
    const float* bp         = (const float*)d_in[4];
    const float* We2d       = (const float*)d_in[5];
    const float* be2d       = (const float*)d_in[6];
    const float* mask_token = (const float*)d_in[7];
    const float* pos        = (const float*)d_in[8];
    const float* Wqkv       = (const float*)d_in[9];
    const float* bqkv       = (const float*)d_in[10];
    const float* Wo         = (const float*)d_in[11];
    const float* bo         = (const float*)d_in[12];
    const float* ln1g       = (const float*)d_in[13];
    const float* ln1b       = (const float*)d_in[14];
    const float* W1         = (const float*)d_in[15];
    const float* b1         = (const float*)d_in[16];
    const float* W2         = (const float*)d_in[17];
    const float* b2         = (const float*)d_in[18];
    const float* ln2g       = (const float*)d_in[19];
    const float* ln2b       = (const float*)d_in[20];
    const float* Wr         = (const float*)d_in[21];
    const float* br         = (const float*)d_in[22];
    float* out = (float*)d_out;

    float  *p_enc, *p_dec, *p_h, *p_qkv, *p_tmp;
    __half *p_vp16, *p_enc16, *p_h16, *p_attn16, *p_ffn16, *p_wt16;
    cudaGetSymbolAddress((void**)&p_vp16,  g_vp16);
    cudaGetSymbolAddress((void**)&p_enc,   g_enc);
    cudaGetSymbolAddress((void**)&p_enc16, g_enc16);
    cudaGetSymbolAddress((void**)&p_dec,   g_dec);
    cudaGetSymbolAddress((void**)&p_h,     g_h);
    cudaGetSymbolAddress((void**)&p_h16,   g_h16);
    cudaGetSymbolAddress((void**)&p_qkv,   g_qkv);
    cudaGetSymbolAddress((void**)&p_attn16,g_attn16);
    cudaGetSymbolAddress((void**)&p_ffn16, g_ffn16);
    cudaGetSymbolAddress((void**)&p_tmp,   g_tmp);
    cudaGetSymbolAddress((void**)&p_wt16,  g_wt16);

    // transpose + fp16-convert all weights: W[K][N] -> WT[N][K]
    launch_transpose(Wp,   p_wt16 + OFF_WP,   OUTD, ENC,  1, 0, 0);
    launch_transpose(We2d, p_wt16 + OFF_WE2D, ENC,  DEC,  1, 0, 0);
    launch_transpose(Wqkv, p_wt16 + OFF_WQKV, DEC, 3*DEC, NLAYERS,
                     (long long)DEC * 3 * DEC, (long long)DEC * 3 * DEC);
    launch_transpose(Wo,   p_wt16 + OFF_WO,   DEC,  DEC,  NLAYERS,
                     (long long)DEC * DEC, (long long)DEC * DEC);
    launch_transpose(W1,   p_wt16 + OFF_W1,   DEC,  FFN,  NLAYERS,
                     (long long)DEC * FFN, (long long)DEC * FFN);
    launch_transpose(W2,   p_wt16 + OFF_W2,   FFN,  DEC,  NLAYERS,
                     (long long)FFN * DEC, (long long)FFN * DEC);
    launch_transpose(Wr,   p_wt16 + OFF_WR,   DEC,  OUTD, 1, 0, 0);

    detect_mask_mode<<<1, 32>>>(mask);
    build_indices<<<BATCH, 32>>>(mask);

    {
        int total = TOK_VIS * OUTD;
        gather_patches<<<(total + 255) / 256, 256>>>(x);
    }

    // encoder projection: [3136,3072] @ [3072,768] (f32 output + f16 copy)
    launch_gemm(0, 2, p_vp16, p_wt16 + OFF_WP, bp, nullptr,
                p_enc, p_enc16, TOK_VIS, ENC, OUTD);
    // enc -> dec: [3136,768] @ [768,512]
    launch_gemm(0, 0, p_enc16, p_wt16 + OFF_WE2D, be2d, nullptr,
                p_dec, nullptr, TOK_VIS, DEC, ENC);

    {
        int total = TOK_FULL * DEC;
        assemble<<<(total + 255) / 256, 256>>>(mask_token, pos);
    }

    for (int l = 0; l < NLAYERS; l++) {
        const __half* Wqkv_l = p_wt16 + OFF_WQKV + (size_t)l * DEC * 3 * DEC;
        const float*  bqkv_l = bqkv + (size_t)l * 3 * DEC;
        const __half* Wo_l   = p_wt16 + OFF_WO + (size_t)l * DEC * DEC;
        const float*  bo_l   = bo   + (size_t)l * DEC;
        const __half* W1_l   = p_wt16 + OFF_W1 + (size_t)l * DEC * FFN;
        const float*  b1_l   = b1   + (size_t)l * FFN;
        const __half* W2_l   = p_wt16 + OFF_W2 + (size_t)l * FFN * DEC;
        const float*  b2_l   = b2   + (size_t)l * DEC;

        launch_gemm(0, 0, p_h16, Wqkv_l, bqkv_l, nullptr,
                    p_qkv, nullptr, TOK_FULL, 3 * DEC, DEC);
        attn_kernel<<<BATCH * NHEADS, 224>>>(p_qkv, p_attn16);
        launch_gemm(2, 0, p_attn16, Wo_l, bo_l, p_h,
                    p_tmp, nullptr, TOK_FULL, DEC, DEC);
        ln_kernel<<<TOK_FULL / 8, 256>>>(p_tmp, ln1g + (size_t)l * DEC,
                                         ln1b + (size_t)l * DEC, p_h, p_h16);

        launch_gemm(1, 1, p_h16, W1_l, b1_l, nullptr,
                    nullptr, p_ffn16, TOK_FULL, FFN, DEC);
        launch_gemm(2, 0, p_ffn16, W2_l, b2_l, p_h,
                    p_tmp, nullptr, TOK_FULL, DEC, FFN);
        ln_kernel<<<TOK_FULL / 8, 256>>>(p_tmp, ln2g + (size_t)l * DEC,
                                         ln2b + (size_t)l * DEC, p_h, p_h16);
    }

    // reconstruction: [12544,512] @ [512,3072]
    launch_gemm(0, 0, p_h16, p_wt16 + OFF_WR, br, nullptr,
                out, nullptr, TOK_FULL, OUTD, DEC);

    const long long recon_elems = (long long)TOK_FULL * OUTD;
    const long long enc_elems   = (long long)TOK_VIS * ENC;
    if ((long long)out_size >= recon_elems + enc_elems) {
        cudaMemcpyAsync(out + recon_elems, p_enc, enc_elems * sizeof(float),
                        cudaMemcpyDeviceToDevice, 0);
    }
}

// round 16
// speedup vs baseline: 1.0303x; 1.0303x over previous
#include <cuda_runtime.h>
#include <cuda_fp16.h>
#include <cstdint>
#include <math.h>

// ---------------- problem constants ----------------
#define BATCH   64
#define NPATCH  196
#define NVIS    49
#define ENC     768
#define DEC     512
#define FFN     2048
#define OUTD    3072      // 16*16*12
#define NLAYERS 8
#define NHEADS  16
#define HD      32
#define IMG     224
#define CIN     12
#define PS      16

#define TOK_FULL (BATCH*NPATCH)   // 12544
#define TOK_VIS  (BATCH*NVIS)     // 3136

// transposed fp16 weight offsets (elements)
#define OFF_WP   0
#define OFF_WE2D (OFF_WP   + OUTD*ENC)
#define OFF_WQKV (OFF_WE2D + ENC*DEC)
#define OFF_WO   (OFF_WQKV + NLAYERS*DEC*3*DEC)
#define OFF_W1   (OFF_WO   + NLAYERS*DEC*DEC)
#define OFF_W2   (OFF_W1   + NLAYERS*DEC*FFN)
#define OFF_WR   (OFF_W2   + NLAYERS*FFN*DEC)
#define WTS_TOTAL (OFF_WR  + DEC*OUTD)

// ---------------- scratch (device globals; no allocation) ----------------
__device__ __half g_vp16 [TOK_VIS * OUTD];
__device__ float  g_enc  [TOK_VIS * ENC];
__device__ __half g_enc16[TOK_VIS * ENC];
__device__ float  g_dec  [TOK_VIS * DEC];
__device__ float  g_h    [TOK_FULL * DEC];
__device__ __half g_h16  [TOK_FULL * DEC];
__device__ float  g_qkv  [TOK_FULL * 3*DEC];
__device__ __half g_attn16[TOK_FULL * DEC];
__device__ __half g_ffn16[TOK_FULL * FFN];
__device__ float  g_tmp  [TOK_FULL * DEC];
__device__ __half g_wt16 [WTS_TOTAL];        // transposed [N][K] fp16 weights
__device__ int    g_vis_idx[TOK_VIS];
__device__ int    g_slot[TOK_FULL];
__device__ int    g_mode;

// ---------------- packed f32x2 helpers (Blackwell) ----------------
__device__ __forceinline__ uint64_t pack2(float lo, float hi) {
    uint64_t r; asm("mov.b64 %0, {%1, %2};" : "=l"(r) : "f"(lo), "f"(hi)); return r;
}
__device__ __forceinline__ void unpack2(float& lo, float& hi, uint64_t v) {
    asm("mov.b64 {%0, %1}, %2;" : "=f"(lo), "=f"(hi) : "l"(v));
}
#define FMA2(d, a, b) \
    asm("fma.rn.f32x2 %0, %1, %2, %0;" : "+l"(d) : "l"(a), "l"(b))

// ---------------- mask dtype detection ----------------
__global__ void detect_mask_mode(const void* mask) {
    if (threadIdx.x != 0 || blockIdx.x != 0) return;
    {
        const int* p = (const int*)mask;
        bool ok = true; int s = 0;
        for (int i = 0; i < NPATCH; i++) { int v = p[i]; if (v != 0 && v != 1) { ok = false; break; } s += v; }
        if (ok && s == NPATCH - NVIS) { g_mode = 0; return; }
    }
    {
        const unsigned char* p = (const unsigned char*)mask;
        int s = 0;
        for (int i = 0; i < NPATCH; i++) s += (p[i] != 0);
        if (s == NPATCH - NVIS) { g_mode = 1; return; }
    }
    g_mode = 2;
}

__global__ void build_indices(const void* mask) {
    int b = blockIdx.x;
    if (threadIdx.x != 0) return;
    int mode = g_mode;
    const int*           pi = (const int*)mask;
    const unsigned char* pb = (const unsigned char*)mask;
    const float*         pf = (const float*)mask;
    int cnt = 0;
    for (int n = 0; n < NPATCH; n++) {
        int idx = b * NPATCH + n;
        bool m;
        if (mode == 0)      m = (pi[idx] != 0);
        else if (mode == 1) m = (pb[idx] != 0);
        else                m = (pf[idx] != 0.0f);
        if (!m) {
            if (cnt < NVIS) g_vis_idx[b * NVIS + cnt] = n;
            g_slot[idx] = cnt;
            cnt++;
        } else {
            g_slot[idx] = -1;
        }
    }
}

// ---------------- gather visible patches (fp16: A of patch GEMM) ----------
__global__ void gather_patches(const float* __restrict__ x) {
    int idx = blockIdx.x * blockDim.x + threadIdx.x;
    if (idx >= TOK_VIS * OUTD) return;
    int f  = idx % OUTD;
    int bv = idx / OUTD;
    int b  = bv / NVIS;
    int n  = g_vis_idx[bv];
    int c  = f >> 8;
    int r  = f & 255;
    int ph = r >> 4, pw = r & 15;
    int hp = n / 14, wp = n % 14;
    g_vp16[idx] = __float2half(x[(((size_t)(b * CIN + c)) * IMG + hp * PS + ph) * IMG + wp * PS + pw]);
}

// ---------------- weight transpose + fp16 convert: W[K][N] -> WT[N][K] -----
__global__ void transpose_h(const float* __restrict__ src, __half* __restrict__ dst,
                            int K, int N, long long sstride, long long dstride) {
    src += (long long)blockIdx.z * sstride;
    dst += (long long)blockIdx.z * dstride;
    __shared__ float t[32][33];
    int n0 = blockIdx.x * 32, k0 = blockIdx.y * 32;
    #pragma unroll
    for (int i = threadIdx.y; i < 32; i += 8)
        t[i][threadIdx.x] = src[(size_t)(k0 + i) * N + n0 + threadIdx.x];
    __syncthreads();
    #pragma unroll
    for (int i = threadIdx.y; i < 32; i += 8)
        dst[(size_t)(n0 + i) * K + k0 + threadIdx.x] = __float2half(t[threadIdx.x][i]);
}

// ---------------- fast exact GELU (A&S 7.1.26 erf, |eps| <= 1.5e-7) --------
__device__ __forceinline__ float gelu_exact(float x) {
    float az = fabsf(x) * 0.70710678118654752f;
    float den = fmaf(0.3275911f, az, 1.0f);
    float t;
    asm("rcp.approx.f32 %0, %1;" : "=f"(t) : "f"(den));
    float p = fmaf(1.061405429f, t, -1.453152027f);
    p = fmaf(p, t, 1.421413741f);
    p = fmaf(p, t, -0.284496736f);
    p = fmaf(p, t, 0.254829592f);
    p = p * t;
    float e = __expf(-az * az);
    float q = 0.5f * x * p * e;
    return (x >= 0.f) ? (x - q) : q;
}

// ---------------- shared mma helpers ----------------
__device__ __forceinline__ void cp_async16(uint32_t dst, const void* src, int srcBytes) {
    asm volatile("cp.async.ca.shared.global [%0], [%1], 16, %2;\n"
                 :: "r"(dst), "l"(src), "r"(srcBytes));
}
__device__ __forceinline__ void cp_commit() {
    asm volatile("cp.async.commit_group;\n");
}
template<int N_>
__device__ __forceinline__ void cp_wait() {
    asm volatile("cp.async.wait_group %0;\n" :: "n"(N_));
}
__device__ __forceinline__ void ldsm_x4(uint32_t& r0, uint32_t& r1, uint32_t& r2, uint32_t& r3,
                                        uint32_t saddr) {
    asm volatile("ldmatrix.sync.aligned.m8n8.x4.shared.b16 {%0,%1,%2,%3}, [%4];\n"
                 : "=r"(r0), "=r"(r1), "=r"(r2), "=r"(r3) : "r"(saddr));
}
__device__ __forceinline__ void mma_f16(float c[4], const uint32_t a[4], const uint32_t b[2]) {
    asm volatile(
        "mma.sync.aligned.m16n8k16.row.col.f32.f16.f16.f32 "
        "{%0,%1,%2,%3}, {%4,%5,%6,%7}, {%8,%9}, {%0,%1,%2,%3};\n"
        : "+f"(c[0]), "+f"(c[1]), "+f"(c[2]), "+f"(c[3])
        : "r"(a[0]), "r"(a[1]), "r"(a[2]), "r"(a[3]), "r"(b[0]), "r"(b[1]));
}

// =====================================================================
// fp16 GEMM (R10 winner): 128x128 block, BK=32, warp tile 64x32,
// ldmatrix.x4 fragment loads, double-buffered cp.async, 2 CTAs/SM.
// N%128==0, K%32==0. M guarded.
// =====================================================================
#define RSW 20
#define TILE_W (128 * RSW)

template<int EPI, int OUT>   // EPI: 0=bias 1=+gelu 2=+residual ; OUT: 0=f32 1=f16 2=both
__global__ __launch_bounds__(256, 2)
void gemm_h(const __half* __restrict__ A, const __half* __restrict__ BT,
            const float* __restrict__ bias, const float* __restrict__ R,
            float* __restrict__ C, __half* __restrict__ C16,
            int M, int N, int K)
{
    __shared__ uint32_t As[2][TILE_W];
    __shared__ uint32_t Bs[2][TILE_W];

    const int tid  = threadIdx.x;
    const int wid  = tid >> 5;
    const int lane = tid & 31;
    const int g    = lane >> 2;
    const int tig  = lane & 3;
    const int wm   = wid & 1;
    const int wn   = wid >> 1;
    const int rowBase = blockIdx.y * 128;
    const int colBase = blockIdx.x * 128;

    float acc[4][4][4];
    #pragma unroll
    for (int mt = 0; mt < 4; mt++)
        #pragma unroll
        for (int nt = 0; nt < 4; nt++)
            #pragma unroll
            for (int r = 0; r < 4; r++) acc[mt][nt][r] = 0.f;

    const uint32_t sA = (uint32_t)__cvta_generic_to_shared(&As[0][0]);
    const uint32_t sB = (uint32_t)__cvta_generic_to_shared(&Bs[0][0]);

    const int ldRow = tid >> 2;
    const int ldC   = tid & 3;
    const int aRow0 = rowBase + ldRow;
    const int aRow1 = rowBase + ldRow + 64;
    const int aOk0  = (aRow0 < M) ? 16 : 0;
    const int aOk1  = (aRow1 < M) ? 16 : 0;
    const int aRc0  = (aRow0 < M) ? aRow0 : 0;
    const int aRc1  = (aRow1 < M) ? aRow1 : 0;
    const int bRow0 = colBase + ldRow;
    const int bRow1 = colBase + ldRow + 64;
    const uint32_t dOff0 = (uint32_t)((ldRow * RSW + ldC * 4) * 4);
    const uint32_t dOff1 = (uint32_t)(((ldRow + 64) * RSW + ldC * 4) * 4);

    uint32_t aAddr[4];
    #pragma unroll
    for (int mt = 0; mt < 4; mt++) {
        int row = wm * 64 + mt * 16 + (lane & 15);
        aAddr[mt] = sA + (uint32_t)((row * RSW + (lane >> 4) * 4) * 4);
    }
    uint32_t bAddr[2];
    #pragma unroll
    for (int p = 0; p < 2; p++) {
        int row = wn * 32 + p * 16 + ((lane >> 4) & 1) * 8 + (lane & 7);
        bAddr[p] = sB + (uint32_t)((row * RSW + ((lane >> 3) & 1) * 4) * 4);
    }

    const int nIters = K >> 5;

    {
        cp_async16(sA + dOff0, A + (size_t)aRc0 * K + ldC * 8, aOk0);
        cp_async16(sA + dOff1, A + (size_t)aRc1 * K + ldC * 8, aOk1);
        cp_async16(sB + dOff0, BT + (size_t)bRow0 * K + ldC * 8, 16);
        cp_async16(sB + dOff1, BT + (size_t)bRow1 * K + ldC * 8, 16);
        cp_commit();
    }

    for (int it = 0; it < nIters; it++) {
        const int buf = it & 1;
        if (it + 1 < nIters) {
            const int nbuf = buf ^ 1;
            const int k0 = (it + 1) << 5;
            const uint32_t bufOff = (uint32_t)(nbuf * TILE_W * 4);
            cp_async16(sA + bufOff + dOff0, A + (size_t)aRc0 * K + k0 + ldC * 8, aOk0);
            cp_async16(sA + bufOff + dOff1, A + (size_t)aRc1 * K + k0 + ldC * 8, aOk1);
            cp_async16(sB + bufOff + dOff0, BT + (size_t)bRow0 * K + k0 + ldC * 8, 16);
            cp_async16(sB + bufOff + dOff1, BT + (size_t)bRow1 * K + k0 + ldC * 8, 16);
            cp_commit();
            cp_wait<1>();
        } else {
            cp_wait<0>();
        }
        __syncthreads();

        const uint32_t bufB = (uint32_t)(buf * TILE_W * 4);
        #pragma unroll
        for (int ks = 0; ks < 2; ks++) {
            const uint32_t ksB = (uint32_t)(ks * 32);
            uint32_t bfrag[4][2];
            #pragma unroll
            for (int p = 0; p < 2; p++) {
                ldsm_x4(bfrag[2 * p][0], bfrag[2 * p][1],
                        bfrag[2 * p + 1][0], bfrag[2 * p + 1][1],
                        bAddr[p] + bufB + ksB);
            }
            uint32_t afrag[4][4];
            #pragma unroll
            for (int mt = 0; mt < 4; mt++) {
                ldsm_x4(afrag[mt][0], afrag[mt][1], afrag[mt][2], afrag[mt][3],
                        aAddr[mt] + bufB + ksB);
            }
            #pragma unroll
            for (int mt = 0; mt < 4; mt++)
                #pragma unroll
                for (int nt = 0; nt < 4; nt++)
                    mma_f16(acc[mt][nt], afrag[mt], bfrag[nt]);
        }
        __syncthreads();
    }

    #pragma unroll
    for (int mt = 0; mt < 4; mt++) {
        int row0 = rowBase + wm * 64 + mt * 16 + g;
        #pragma unroll
        for (int nt = 0; nt < 4; nt++) {
            int col = colBase + wn * 32 + nt * 8 + tig * 2;
            float b0 = bias[col], b1 = bias[col + 1];
            #pragma unroll
            for (int half_ = 0; half_ < 2; half_++) {
                int row = row0 + half_ * 8;
                if (row >= M) continue;
                float v0 = acc[mt][nt][half_ * 2 + 0] + b0;
                float v1 = acc[mt][nt][half_ * 2 + 1] + b1;
                if (EPI == 1) { v0 = gelu_exact(v0); v1 = gelu_exact(v1); }
                if (EPI == 2) {
                    float2 rv = *(const float2*)(R + (size_t)row * N + col);
                    v0 += rv.x; v1 += rv.y;
                }
                if (OUT == 0 || OUT == 2) {
                    float2 o; o.x = v0; o.y = v1;
                    *(float2*)(C + (size_t)row * N + col) = o;
                }
                if (OUT == 1 || OUT == 2) {
                    *(__half2*)(C16 + (size_t)row * N + col) = __floats2half2_rn(v0, v1);
                }
            }
        }
    }
}

// ---------------- mask-token assembly + pos embed (dual write) ------------
__global__ void assemble(const float* __restrict__ mask_token,
                         const float* __restrict__ pos) {
    int idx = blockIdx.x * blockDim.x + threadIdx.x;
    if (idx >= TOK_FULL * DEC) return;
    int d  = idx & (DEC - 1);
    int bn = idx >> 9;
    int n  = bn % NPATCH;
    int b  = bn / NPATCH;
    int sl = g_slot[bn];
    float v = (sl < 0) ? mask_token[d] : g_dec[(size_t)(b * NVIS + sl) * DEC + d];
    v += pos[n * DEC + d];
    g_h[idx]   = v;
    g_h16[idx] = __float2half(v);
}

// ---------------- attention: packed f32x2 FMA, split score chains ---------
// Scores tiny (|d| <~ 1): softmax without max-subtraction is identical math.
// One key per iteration (R14 structure; R15's 2-key unroll spilled), but the
// score dot product uses FOUR independent FMA2 chains of depth 4 instead of
// two chains of depth 8 — halves the dependent-chain latency per key at a
// cost of ~4 registers. Summation order within the dot product changes
// (fp32 rounding noise only).
__global__ __launch_bounds__(224)
void attn_kernel(const float* __restrict__ qkv, __half* __restrict__ out16) {
    const int S = NPATCH;
    int b = blockIdx.x >> 4;
    int h = blockIdx.x & 15;
    int tid = threadIdx.x;
    __shared__ float4 Kt4[64][8];
    __shared__ float4 Vt4[64][8];

    // q packed: 16 f32x2 pairs (32 floats)
    uint64_t q2[16];
    const float* qbase = qkv + (size_t)(b * S) * (3 * DEC) + h * HD;
    if (tid < S) {
        const float4* qp = (const float4*)(qbase + (size_t)tid * (3 * DEC));
        #pragma unroll
        for (int i = 0; i < 8; i++) {
            float4 qv = qp[i];
            q2[2 * i]     = pack2(qv.x, qv.y);
            q2[2 * i + 1] = pack2(qv.z, qv.w);
        }
    }
    // o accumulators packed: 16 f32x2 pairs (32 floats)
    uint64_t o2[16];
    #pragma unroll
    for (int i = 0; i < 16; i++) o2[i] = 0ull;
    float s = 0.f;
    const float scale = 0.17677669529663689f; // 1/sqrt(32)

    for (int j0 = 0; j0 < S; j0 += 64) {
        int jn = min(64, S - j0);
        for (int idx = tid; idx < jn * 8; idx += blockDim.x) {
            int jj = idx >> 3, kk = idx & 7;
            const float4* base = (const float4*)(qkv + (size_t)(b * S + j0 + jj) * (3 * DEC) + h * HD);
            Kt4[jj][kk] = base[DEC / 4 + kk];
            Vt4[jj][kk] = base[2 * DEC / 4 + kk];
        }
        __syncthreads();
        if (tid < S) {
            for (int jj = 0; jj < jn; jj++) {
                const ulonglong2* kt = (const ulonglong2*)(&Kt4[jj][0]);
                uint64_t d0 = 0ull, d1 = 0ull, d2 = 0ull, d3 = 0ull;
                #pragma unroll
                for (int i = 0; i < 4; i++) {
                    ulonglong2 kva = kt[2 * i];
                    ulonglong2 kvb = kt[2 * i + 1];
                    FMA2(d0, q2[4 * i],     kva.x);
                    FMA2(d1, q2[4 * i + 1], kva.y);
                    FMA2(d2, q2[4 * i + 2], kvb.x);
                    FMA2(d3, q2[4 * i + 3], kvb.y);
                }
                float a0, a1, a2, a3, a4, a5, a6, a7;
                unpack2(a0, a1, d0); unpack2(a2, a3, d1);
                unpack2(a4, a5, d2); unpack2(a6, a7, d3);
                float d = (((a0 + a2) + (a4 + a6)) + ((a1 + a3) + (a5 + a7))) * scale;
                float p = __expf(d);
                s += p;
                uint64_t pp = pack2(p, p);
                const ulonglong2* vt = (const ulonglong2*)(&Vt4[jj][0]);
                #pragma unroll
                for (int i = 0; i < 8; i++) {
                    ulonglong2 vv = vt[i];
                    FMA2(o2[2 * i],     pp, vv.x);
                    FMA2(o2[2 * i + 1], pp, vv.y);
                }
            }
        }
        __syncthreads();
    }
    if (tid < S) {
        float inv = 1.f / s;
        __half2* op = (__half2*)(out16 + (size_t)(b * S + tid) * DEC + h * HD);
        #pragma unroll
        for (int i = 0; i < 8; i++) {
            float x0, x1, x2, x3;
            unpack2(x0, x1, o2[2 * i]);
            unpack2(x2, x3, o2[2 * i + 1]);
            op[2 * i]     = __floats2half2_rn(x0 * inv, x1 * inv);
            op[2 * i + 1] = __floats2half2_rn(x2 * inv, x3 * inv);
        }
    }
}

// ---------------- layernorm: warp-per-row, 8 rows/CTA, shuffle-only -------
__global__ __launch_bounds__(256)
void ln_kernel(const float* __restrict__ X, const float* __restrict__ g,
               const float* __restrict__ bta,
               float* __restrict__ Y, __half* __restrict__ Y16) {
    int warp = threadIdx.x >> 5;
    int lane = threadIdx.x & 31;
    int row  = blockIdx.x * 8 + warp;

    const float4* x4 = (const float4*)(X + (size_t)row * DEC);
    const float4* g4 = (const float4*)g;
    const float4* b4 = (const float4*)bta;

    float4 v[4];
    float sum = 0.f, sq = 0.f;
    #pragma unroll
    for (int i = 0; i < 4; i++) {
        v[i] = x4[lane + 32 * i];
        sum += (v[i].x + v[i].y) + (v[i].z + v[i].w);
        sq  = fmaf(v[i].x, v[i].x, sq);
        sq  = fmaf(v[i].y, v[i].y, sq);
        sq  = fmaf(v[i].z, v[i].z, sq);
        sq  = fmaf(v[i].w, v[i].w, sq);
    }
    #pragma unroll
    for (int o = 16; o > 0; o >>= 1) {
        sum += __shfl_xor_sync(0xffffffffu, sum, o);
        sq  += __shfl_xor_sync(0xffffffffu, sq,  o);
    }
    float mean = sum * (1.f / DEC);
    float var  = sq * (1.f / DEC) - mean * mean;
    float r = rsqrtf(var + 1e-5f);

    float4*  y4  = (float4*)(Y + (size_t)row * DEC);
    __half2* y16 = (__half2*)(Y16 + (size_t)row * DEC);
    #pragma unroll
    for (int i = 0; i < 4; i++) {
        float4 gv = g4[lane + 32 * i];
        float4 bv = b4[lane + 32 * i];
        float4 o;
        o.x = (v[i].x - mean) * r * gv.x + bv.x;
        o.y = (v[i].y - mean) * r * gv.y + bv.y;
        o.z = (v[i].z - mean) * r * gv.z + bv.z;
        o.w = (v[i].w - mean) * r * gv.w + bv.w;
        y4[lane + 32 * i] = o;
        y16[(lane + 32 * i) * 2]     = __floats2half2_rn(o.x, o.y);
        y16[(lane + 32 * i) * 2 + 1] = __floats2half2_rn(o.z, o.w);
    }
}

// ---------------- host orchestration ----------------
static void launch_gemm(int epi, int outm,
                        const __half* A, const __half* BT, const float* bias,
                        const float* R, float* C, __half* C16,
                        int M, int N, int K) {
    dim3 grid(N / 128, (M + 127) / 128);
    #define GC(E, O) gemm_h<E, O><<<grid, 256>>>(A, BT, bias, R, C, C16, M, N, K)
    if (epi == 0) { if (outm == 0) GC(0,0); else if (outm == 1) GC(0,1); else GC(0,2); }
    else if (epi == 1) { if (outm == 0) GC(1,0); else if (outm == 1) GC(1,1); else GC(1,2); }
    else { if (outm == 0) GC(2,0); else if (outm == 1) GC(2,1); else GC(2,2); }
    #undef GC
}

static void launch_transpose(const float* src, __half* dst, int K, int N,
                             int layers, long long sstride, long long dstride) {
    dim3 grid(N / 32, K / 32, layers);
    transpose_h<<<grid, dim3(32, 8)>>>(src, dst, K, N, sstride, dstride);
}

extern "C" void kernel_launch(void* const* d_in, const int* in_sizes, int n_in,
                              void* d_out, int out_size) {
    const float* x          = (const float*)d_in[0];
    const void*  mask       = d_in[1];
    const float* Wp         = (const float*)d_in[3];
    const float* bp         = (const float*)d_in[4];
    const float* We2d       = (const float*)d_in[5];
    const float* be2d       = (const float*)d_in[6];
    const float* mask_token = (const float*)d_in[7];
    const float* pos        = (const float*)d_in[8];
    const float* Wqkv       = (const float*)d_in[9];
    const float* bqkv       = (const float*)d_in[10];
    const float* Wo         = (const float*)d_in[11];
    const float* bo         = (const float*)d_in[12];
    const float* ln1g       = (const float*)d_in[13];
    const float* ln1b       = (const float*)d_in[14];
    const float* W1         = (const float*)d_in[15];
    const float* b1         = (const float*)d_in[16];
    const float* W2         = (const float*)d_in[17];
    const float* b2         = (const float*)d_in[18];
    const float* ln2g       = (const float*)d_in[19];
    const float* ln2b       = (const float*)d_in[20];
    const float* Wr         = (const float*)d_in[21];
    const float* br         = (const float*)d_in[22];
    float* out = (float*)d_out;

    float  *p_enc, *p_dec, *p_h, *p_qkv, *p_tmp;
    __half *p_vp16, *p_enc16, *p_h16, *p_attn16, *p_ffn16, *p_wt16;
    cudaGetSymbolAddress((void**)&p_vp16,  g_vp16);
    cudaGetSymbolAddress((void**)&p_enc,   g_enc);
    cudaGetSymbolAddress((void**)&p_enc16, g_enc16);
    cudaGetSymbolAddress((void**)&p_dec,   g_dec);
    cudaGetSymbolAddress((void**)&p_h,     g_h);
    cudaGetSymbolAddress((void**)&p_h16,   g_h16);
    cudaGetSymbolAddress((void**)&p_qkv,   g_qkv);
    cudaGetSymbolAddress((void**)&p_attn16,g_attn16);
    cudaGetSymbolAddress((void**)&p_ffn16, g_ffn16);
    cudaGetSymbolAddress((void**)&p_tmp,   g_tmp);
    cudaGetSymbolAddress((void**)&p_wt16,  g_wt16);

    // transpose + fp16-convert all weights: W[K][N] -> WT[N][K]
    launch_transpose(Wp,   p_wt16 + OFF_WP,   OUTD, ENC,  1, 0, 0);
    launch_transpose(We2d, p_wt16 + OFF_WE2D, ENC,  DEC,  1, 0, 0);
    launch_transpose(Wqkv, p_wt16 + OFF_WQKV, DEC, 3*DEC, NLAYERS,
                     (long long)DEC * 3 * DEC, (long long)DEC * 3 * DEC);
    launch_transpose(Wo,   p_wt16 + OFF_WO,   DEC,  DEC,  NLAYERS,
                     (long long)DEC * DEC, (long long)DEC * DEC);
    launch_transpose(W1,   p_wt16 + OFF_W1,   DEC,  FFN,  NLAYERS,
                     (long long)DEC * FFN, (long long)DEC * FFN);
    launch_transpose(W2,   p_wt16 + OFF_W2,   FFN,  DEC,  NLAYERS,
                     (long long)FFN * DEC, (long long)FFN * DEC);
    launch_transpose(Wr,   p_wt16 + OFF_WR,   DEC,  OUTD, 1, 0, 0);

    detect_mask_mode<<<1, 32>>>(mask);
    build_indices<<<BATCH, 32>>>(mask);

    {
        int total = TOK_VIS * OUTD;
        gather_patches<<<(total + 255) / 256, 256>>>(x);
    }

    // encoder projection: [3136,3072] @ [3072,768] (f32 output + f16 copy)
    launch_gemm(0, 2, p_vp16, p_wt16 + OFF_WP, bp, nullptr,
                p_enc, p_enc16, TOK_VIS, ENC, OUTD);
    // enc -> dec: [3136,768] @ [768,512]
    launch_gemm(0, 0, p_enc16, p_wt16 + OFF_WE2D, be2d, nullptr,
                p_dec, nullptr, TOK_VIS, DEC, ENC);

    {
        int total = TOK_FULL * DEC;
        assemble<<<(total + 255) / 256, 256>>>(mask_token, pos);
    }

    for (int l = 0; l < NLAYERS; l++) {
        const __half* Wqkv_l = p_wt16 + OFF_WQKV + (size_t)l * DEC * 3 * DEC;
        const float*  bqkv_l = bqkv + (size_t)l * 3 * DEC;
        const __half* Wo_l   = p_wt16 + OFF_WO + (size_t)l * DEC * DEC;
        const float*  bo_l   = bo   + (size_t)l * DEC;
        const __half* W1_l   = p_wt16 + OFF_W1 + (size_t)l * DEC * FFN;
        const float*  b1_l   = b1   + (size_t)l * FFN;
        const __half* W2_l   = p_wt16 + OFF_W2 + (size_t)l * FFN * DEC;
        const float*  b2_l   = b2   + (size_t)l * DEC;

        launch_gemm(0, 0, p_h16, Wqkv_l, bqkv_l, nullptr,
                    p_qkv, nullptr, TOK_FULL, 3 * DEC, DEC);
        attn_kernel<<<BATCH * NHEADS, 224>>>(p_qkv, p_attn16);
        launch_gemm(2, 0, p_attn16, Wo_l, bo_l, p_h,
                    p_tmp, nullptr, TOK_FULL, DEC, DEC);
        ln_kernel<<<TOK_FULL / 8, 256>>>(p_tmp, ln1g + (size_t)l * DEC,
                                         ln1b + (size_t)l * DEC, p_h, p_h16);

        launch_gemm(1, 1, p_h16, W1_l, b1_l, nullptr,
                    nullptr, p_ffn16, TOK_FULL, FFN, DEC);
        launch_gemm(2, 0, p_ffn16, W2_l, b2_l, p_h,
                    p_tmp, nullptr, TOK_FULL, DEC, FFN);
        ln_kernel<<<TOK_FULL / 8, 256>>>(p_tmp, ln2g + (size_t)l * DEC,
                                         ln2b + (size_t)l * DEC, p_h, p_h16);
    }

    // reconstruction: [12544,512] @ [512,3072]
    launch_gemm(0, 0, p_h16, p_wt16 + OFF_WR, br, nullptr,
                out, nullptr, TOK_FULL, OUTD, DEC);

    const long long recon_elems = (long long)TOK_FULL * OUTD;
    const long long enc_elems   = (long long)TOK_VIS * ENC;
    if ((long long)out_size >= recon_elems + enc_elems) {
        cudaMemcpyAsync(out + recon_elems, p_enc, enc_elems * sizeof(float),
                        cudaMemcpyDeviceToDevice, 0);
    }
}

// round 17
// speedup vs baseline: 1.0468x; 1.0160x over previous
#include <cuda_runtime.h>
#include <cuda_fp16.h>
#include <cstdint>
#include <math.h>

// ---------------- problem constants ----------------
#define BATCH   64
#define NPATCH  196
#define NVIS    49
#define ENC     768
#define DEC     512
#define FFN     2048
#define OUTD    3072      // 16*16*12
#define NLAYERS 8
#define NHEADS  16
#define HD      32
#define IMG     224
#define CIN     12
#define PS      16

#define TOK_FULL (BATCH*NPATCH)   // 12544
#define TOK_VIS  (BATCH*NVIS)     // 3136

// transposed fp16 weight offsets (elements)
#define OFF_WP   0
#define OFF_WE2D (OFF_WP   + OUTD*ENC)
#define OFF_WQKV (OFF_WE2D + ENC*DEC)
#define OFF_WO   (OFF_WQKV + NLAYERS*DEC*3*DEC)
#define OFF_W1   (OFF_WO   + NLAYERS*DEC*DEC)
#define OFF_W2   (OFF_W1   + NLAYERS*DEC*FFN)
#define OFF_WR   (OFF_W2   + NLAYERS*FFN*DEC)
#define WTS_TOTAL (OFF_WR  + DEC*OUTD)

// ---------------- scratch (device globals; no allocation) ----------------
__device__ __half g_vp16 [TOK_VIS * OUTD];
__device__ float  g_enc  [TOK_VIS * ENC];
__device__ __half g_enc16[TOK_VIS * ENC];
__device__ float  g_dec  [TOK_VIS * DEC];
__device__ float  g_h    [TOK_FULL * DEC];
__device__ __half g_h16  [TOK_FULL * DEC];
__device__ __half g_qkv16[TOK_FULL * 3*DEC];
__device__ __half g_attn16[TOK_FULL * DEC];
__device__ __half g_ffn16[TOK_FULL * FFN];
__device__ float  g_tmp  [TOK_FULL * DEC];
__device__ __half g_wt16 [WTS_TOTAL];        // transposed [N][K] fp16 weights
__device__ int    g_vis_idx[TOK_VIS];
__device__ int    g_slot[TOK_FULL];
__device__ int    g_mode;

// ---------------- packed f32x2 helpers (Blackwell) ----------------
__device__ __forceinline__ uint64_t pack2(float lo, float hi) {
    uint64_t r; asm("mov.b64 %0, {%1, %2};" : "=l"(r) : "f"(lo), "f"(hi)); return r;
}
__device__ __forceinline__ void unpack2(float& lo, float& hi, uint64_t v) {
    asm("mov.b64 {%0, %1}, %2;" : "=f"(lo), "=f"(hi) : "l"(v));
}
#define FMA2(d, a, b) \
    asm("fma.rn.f32x2 %0, %1, %2, %0;" : "+l"(d) : "l"(a), "l"(b))

// ---------------- mask dtype detection ----------------
__global__ void detect_mask_mode(const void* mask) {
    if (threadIdx.x != 0 || blockIdx.x != 0) return;
    {
        const int* p = (const int*)mask;
        bool ok = true; int s = 0;
        for (int i = 0; i < NPATCH; i++) { int v = p[i]; if (v != 0 && v != 1) { ok = false; break; } s += v; }
        if (ok && s == NPATCH - NVIS) { g_mode = 0; return; }
    }
    {
        const unsigned char* p = (const unsigned char*)mask;
        int s = 0;
        for (int i = 0; i < NPATCH; i++) s += (p[i] != 0);
        if (s == NPATCH - NVIS) { g_mode = 1; return; }
    }
    g_mode = 2;
}

__global__ void build_indices(const void* mask) {
    int b = blockIdx.x;
    if (threadIdx.x != 0) return;
    int mode = g_mode;
    const int*           pi = (const int*)mask;
    const unsigned char* pb = (const unsigned char*)mask;
    const float*         pf = (const float*)mask;
    int cnt = 0;
    for (int n = 0; n < NPATCH; n++) {
        int idx = b * NPATCH + n;
        bool m;
        if (mode == 0)      m = (pi[idx] != 0);
        else if (mode == 1) m = (pb[idx] != 0);
        else                m = (pf[idx] != 0.0f);
        if (!m) {
            if (cnt < NVIS) g_vis_idx[b * NVIS + cnt] = n;
            g_slot[idx] = cnt;
            cnt++;
        } else {
            g_slot[idx] = -1;
        }
    }
}

// ---------------- gather visible patches (fp16: A of patch GEMM) ----------
__global__ void gather_patches(const float* __restrict__ x) {
    int idx = blockIdx.x * blockDim.x + threadIdx.x;
    if (idx >= TOK_VIS * OUTD) return;
    int f  = idx % OUTD;
    int bv = idx / OUTD;
    int b  = bv / NVIS;
    int n  = g_vis_idx[bv];
    int c  = f >> 8;
    int r  = f & 255;
    int ph = r >> 4, pw = r & 15;
    int hp = n / 14, wp = n % 14;
    g_vp16[idx] = __float2half(x[(((size_t)(b * CIN + c)) * IMG + hp * PS + ph) * IMG + wp * PS + pw]);
}

// ---------------- weight transpose + fp16 convert: W[K][N] -> WT[N][K] -----
__global__ void transpose_h(const float* __restrict__ src, __half* __restrict__ dst,
                            int K, int N, long long sstride, long long dstride) {
    src += (long long)blockIdx.z * sstride;
    dst += (long long)blockIdx.z * dstride;
    __shared__ float t[32][33];
    int n0 = blockIdx.x * 32, k0 = blockIdx.y * 32;
    #pragma unroll
    for (int i = threadIdx.y; i < 32; i += 8)
        t[i][threadIdx.x] = src[(size_t)(k0 + i) * N + n0 + threadIdx.x];
    __syncthreads();
    #pragma unroll
    for (int i = threadIdx.y; i < 32; i += 8)
        dst[(size_t)(n0 + i) * K + k0 + threadIdx.x] = __float2half(t[threadIdx.x][i]);
}

// ---------------- fast exact GELU (A&S 7.1.26 erf, |eps| <= 1.5e-7) --------
__device__ __forceinline__ float gelu_exact(float x) {
    float az = fabsf(x) * 0.70710678118654752f;
    float den = fmaf(0.3275911f, az, 1.0f);
    float t;
    asm("rcp.approx.f32 %0, %1;" : "=f"(t) : "f"(den));
    float p = fmaf(1.061405429f, t, -1.453152027f);
    p = fmaf(p, t, 1.421413741f);
    p = fmaf(p, t, -0.284496736f);
    p = fmaf(p, t, 0.254829592f);
    p = p * t;
    float e = __expf(-az * az);
    float q = 0.5f * x * p * e;
    return (x >= 0.f) ? (x - q) : q;
}

// ---------------- shared mma helpers ----------------
__device__ __forceinline__ void cp_async16(uint32_t dst, const void* src, int srcBytes) {
    asm volatile("cp.async.ca.shared.global [%0], [%1], 16, %2;\n"
                 :: "r"(dst), "l"(src), "r"(srcBytes));
}
__device__ __forceinline__ void cp_commit() {
    asm volatile("cp.async.commit_group;\n");
}
template<int N_>
__device__ __forceinline__ void cp_wait() {
    asm volatile("cp.async.wait_group %0;\n" :: "n"(N_));
}
__device__ __forceinline__ void ldsm_x4(uint32_t& r0, uint32_t& r1, uint32_t& r2, uint32_t& r3,
                                        uint32_t saddr) {
    asm volatile("ldmatrix.sync.aligned.m8n8.x4.shared.b16 {%0,%1,%2,%3}, [%4];\n"
                 : "=r"(r0), "=r"(r1), "=r"(r2), "=r"(r3) : "r"(saddr));
}
__device__ __forceinline__ void mma_f16(float c[4], const uint32_t a[4], const uint32_t b[2]) {
    asm volatile(
        "mma.sync.aligned.m16n8k16.row.col.f32.f16.f16.f32 "
        "{%0,%1,%2,%3}, {%4,%5,%6,%7}, {%8,%9}, {%0,%1,%2,%3};\n"
        : "+f"(c[0]), "+f"(c[1]), "+f"(c[2]), "+f"(c[3])
        : "r"(a[0]), "r"(a[1]), "r"(a[2]), "r"(a[3]), "r"(b[0]), "r"(b[1]));
}

// =====================================================================
// fp16 GEMM (R10 winner): 128x128 block, BK=32, warp tile 64x32,
// ldmatrix.x4 fragment loads, double-buffered cp.async, 2 CTAs/SM.
// N%128==0, K%32==0. M guarded.
// =====================================================================
#define RSW 20
#define TILE_W (128 * RSW)

template<int EPI, int OUT>   // EPI: 0=bias 1=+gelu 2=+residual ; OUT: 0=f32 1=f16 2=both
__global__ __launch_bounds__(256, 2)
void gemm_h(const __half* __restrict__ A, const __half* __restrict__ BT,
            const float* __restrict__ bias, const float* __restrict__ R,
            float* __restrict__ C, __half* __restrict__ C16,
            int M, int N, int K)
{
    __shared__ uint32_t As[2][TILE_W];
    __shared__ uint32_t Bs[2][TILE_W];

    const int tid  = threadIdx.x;
    const int wid  = tid >> 5;
    const int lane = tid & 31;
    const int g    = lane >> 2;
    const int tig  = lane & 3;
    const int wm   = wid & 1;
    const int wn   = wid >> 1;
    const int rowBase = blockIdx.y * 128;
    const int colBase = blockIdx.x * 128;

    float acc[4][4][4];
    #pragma unroll
    for (int mt = 0; mt < 4; mt++)
        #pragma unroll
        for (int nt = 0; nt < 4; nt++)
            #pragma unroll
            for (int r = 0; r < 4; r++) acc[mt][nt][r] = 0.f;

    const uint32_t sA = (uint32_t)__cvta_generic_to_shared(&As[0][0]);
    const uint32_t sB = (uint32_t)__cvta_generic_to_shared(&Bs[0][0]);

    const int ldRow = tid >> 2;
    const int ldC   = tid & 3;
    const int aRow0 = rowBase + ldRow;
    const int aRow1 = rowBase + ldRow + 64;
    const int aOk0  = (aRow0 < M) ? 16 : 0;
    const int aOk1  = (aRow1 < M) ? 16 : 0;
    const int aRc0  = (aRow0 < M) ? aRow0 : 0;
    const int aRc1  = (aRow1 < M) ? aRow1 : 0;
    const int bRow0 = colBase + ldRow;
    const int bRow1 = colBase + ldRow + 64;
    const uint32_t dOff0 = (uint32_t)((ldRow * RSW + ldC * 4) * 4);
    const uint32_t dOff1 = (uint32_t)(((ldRow + 64) * RSW + ldC * 4) * 4);

    uint32_t aAddr[4];
    #pragma unroll
    for (int mt = 0; mt < 4; mt++) {
        int row = wm * 64 + mt * 16 + (lane & 15);
        aAddr[mt] = sA + (uint32_t)((row * RSW + (lane >> 4) * 4) * 4);
    }
    uint32_t bAddr[2];
    #pragma unroll
    for (int p = 0; p < 2; p++) {
        int row = wn * 32 + p * 16 + ((lane >> 4) & 1) * 8 + (lane & 7);
        bAddr[p] = sB + (uint32_t)((row * RSW + ((lane >> 3) & 1) * 4) * 4);
    }

    const int nIters = K >> 5;

    {
        cp_async16(sA + dOff0, A + (size_t)aRc0 * K + ldC * 8, aOk0);
        cp_async16(sA + dOff1, A + (size_t)aRc1 * K + ldC * 8, aOk1);
        cp_async16(sB + dOff0, BT + (size_t)bRow0 * K + ldC * 8, 16);
        cp_async16(sB + dOff1, BT + (size_t)bRow1 * K + ldC * 8, 16);
        cp_commit();
    }

    for (int it = 0; it < nIters; it++) {
        const int buf = it & 1;
        if (it + 1 < nIters) {
            const int nbuf = buf ^ 1;
            const int k0 = (it + 1) << 5;
            const uint32_t bufOff = (uint32_t)(nbuf * TILE_W * 4);
            cp_async16(sA + bufOff + dOff0, A + (size_t)aRc0 * K + k0 + ldC * 8, aOk0);
            cp_async16(sA + bufOff + dOff1, A + (size_t)aRc1 * K + k0 + ldC * 8, aOk1);
            cp_async16(sB + bufOff + dOff0, BT + (size_t)bRow0 * K + k0 + ldC * 8, 16);
            cp_async16(sB + bufOff + dOff1, BT + (size_t)bRow1 * K + k0 + ldC * 8, 16);
            cp_commit();
            cp_wait<1>();
        } else {
            cp_wait<0>();
        }
        __syncthreads();

        const uint32_t bufB = (uint32_t)(buf * TILE_W * 4);
        #pragma unroll
        for (int ks = 0; ks < 2; ks++) {
            const uint32_t ksB = (uint32_t)(ks * 32);
            uint32_t bfrag[4][2];
            #pragma unroll
            for (int p = 0; p < 2; p++) {
                ldsm_x4(bfrag[2 * p][0], bfrag[2 * p][1],
                        bfrag[2 * p + 1][0], bfrag[2 * p + 1][1],
                        bAddr[p] + bufB + ksB);
            }
            uint32_t afrag[4][4];
            #pragma unroll
            for (int mt = 0; mt < 4; mt++) {
                ldsm_x4(afrag[mt][0], afrag[mt][1], afrag[mt][2], afrag[mt][3],
                        aAddr[mt] + bufB + ksB);
            }
            #pragma unroll
            for (int mt = 0; mt < 4; mt++)
                #pragma unroll
                for (int nt = 0; nt < 4; nt++)
                    mma_f16(acc[mt][nt], afrag[mt], bfrag[nt]);
        }
        __syncthreads();
    }

    #pragma unroll
    for (int mt = 0; mt < 4; mt++) {
        int row0 = rowBase + wm * 64 + mt * 16 + g;
        #pragma unroll
        for (int nt = 0; nt < 4; nt++) {
            int col = colBase + wn * 32 + nt * 8 + tig * 2;
            float b0 = bias[col], b1 = bias[col + 1];
            #pragma unroll
            for (int half_ = 0; half_ < 2; half_++) {
                int row = row0 + half_ * 8;
                if (row >= M) continue;
                float v0 = acc[mt][nt][half_ * 2 + 0] + b0;
                float v1 = acc[mt][nt][half_ * 2 + 1] + b1;
                if (EPI == 1) { v0 = gelu_exact(v0); v1 = gelu_exact(v1); }
                if (EPI == 2) {
                    float2 rv = *(const float2*)(R + (size_t)row * N + col);
                    v0 += rv.x; v1 += rv.y;
                }
                if (OUT == 0 || OUT == 2) {
                    float2 o; o.x = v0; o.y = v1;
                    *(float2*)(C + (size_t)row * N + col) = o;
                }
                if (OUT == 1 || OUT == 2) {
                    *(__half2*)(C16 + (size_t)row * N + col) = __floats2half2_rn(v0, v1);
                }
            }
        }
    }
}

// ---------------- mask-token assembly + pos embed (dual write) ------------
__global__ void assemble(const float* __restrict__ mask_token,
                         const float* __restrict__ pos) {
    int idx = blockIdx.x * blockDim.x + threadIdx.x;
    if (idx >= TOK_FULL * DEC) return;
    int d  = idx & (DEC - 1);
    int bn = idx >> 9;
    int n  = bn % NPATCH;
    int b  = bn / NPATCH;
    int sl = g_slot[bn];
    float v = (sl < 0) ? mask_token[d] : g_dec[(size_t)(b * NVIS + sl) * DEC + d];
    v += pos[n * DEC + d];
    g_h[idx]   = v;
    g_h16[idx] = __float2half(v);
}

// ---------------- attention: fp16 qkv in, f32 math (R14 inner loop) -------
// Scores tiny (|d| <~ 1): softmax without max-subtraction is identical math.
// q/K/V arrive as fp16 (halved gmem traffic); converted to f32 once at load/
// staging. Inner loop identical to the R14 winner (two FMA2 chains, depth 8).
__global__ __launch_bounds__(224)
void attn_kernel(const __half* __restrict__ qkv, __half* __restrict__ out16) {
    const int S = NPATCH;
    int b = blockIdx.x >> 4;
    int h = blockIdx.x & 15;
    int tid = threadIdx.x;
    __shared__ float4 Kt4[64][8];
    __shared__ float4 Vt4[64][8];

    // q: 32 halves = 4x uint4; convert to 16 packed f32 pairs
    uint64_t q2[16];
    const __half* qbase = qkv + (size_t)(b * S) * (3 * DEC) + h * HD;
    if (tid < S) {
        const uint4* qp = (const uint4*)(qbase + (size_t)tid * (3 * DEC));
        #pragma unroll
        for (int i = 0; i < 4; i++) {
            uint4 w = qp[i];
            float2 f0 = __half22float2(*(__half2*)&w.x);
            float2 f1 = __half22float2(*(__half2*)&w.y);
            float2 f2 = __half22float2(*(__half2*)&w.z);
            float2 f3 = __half22float2(*(__half2*)&w.w);
            q2[4 * i]     = pack2(f0.x, f0.y);
            q2[4 * i + 1] = pack2(f1.x, f1.y);
            q2[4 * i + 2] = pack2(f2.x, f2.y);
            q2[4 * i + 3] = pack2(f3.x, f3.y);
        }
    }
    uint64_t o2[16];
    #pragma unroll
    for (int i = 0; i < 16; i++) o2[i] = 0ull;
    float s = 0.f;
    const float scale = 0.17677669529663689f; // 1/sqrt(32)

    for (int j0 = 0; j0 < S; j0 += 64) {
        int jn = min(64, S - j0);
        // stage K/V: read 4-half chunks (uint2), convert, store float4 tiles
        for (int idx = tid; idx < jn * 8; idx += blockDim.x) {
            int jj = idx >> 3, kk = idx & 7;
            const __half* base = qkv + (size_t)(b * S + j0 + jj) * (3 * DEC) + h * HD;
            uint2 kw = ((const uint2*)(base + DEC))[kk];
            uint2 vw = ((const uint2*)(base + 2 * DEC))[kk];
            float2 k0 = __half22float2(*(__half2*)&kw.x);
            float2 k1 = __half22float2(*(__half2*)&kw.y);
            float2 v0 = __half22float2(*(__half2*)&vw.x);
            float2 v1 = __half22float2(*(__half2*)&vw.y);
            Kt4[jj][kk] = make_float4(k0.x, k0.y, k1.x, k1.y);
            Vt4[jj][kk] = make_float4(v0.x, v0.y, v1.x, v1.y);
        }
        __syncthreads();
        if (tid < S) {
            for (int jj = 0; jj < jn; jj++) {
                const ulonglong2* kt = (const ulonglong2*)(&Kt4[jj][0]);
                uint64_t d0 = 0ull, d1 = 0ull;
                #pragma unroll
                for (int i = 0; i < 8; i++) {
                    ulonglong2 kv = kt[i];
                    FMA2(d0, q2[2 * i],     kv.x);
                    FMA2(d1, q2[2 * i + 1], kv.y);
                }
                float a0, a1, a2, a3;
                unpack2(a0, a1, d0);
                unpack2(a2, a3, d1);
                float d = ((a0 + a2) + (a1 + a3)) * scale;
                float p = __expf(d);
                s += p;
                uint64_t pp = pack2(p, p);
                const ulonglong2* vt = (const ulonglong2*)(&Vt4[jj][0]);
                #pragma unroll
                for (int i = 0; i < 8; i++) {
                    ulonglong2 vv = vt[i];
                    FMA2(o2[2 * i],     pp, vv.x);
                    FMA2(o2[2 * i + 1], pp, vv.y);
                }
            }
        }
        __syncthreads();
    }
    if (tid < S) {
        float inv = 1.f / s;
        __half2* op = (__half2*)(out16 + (size_t)(b * S + tid) * DEC + h * HD);
        #pragma unroll
        for (int i = 0; i < 8; i++) {
            float x0, x1, x2, x3;
            unpack2(x0, x1, o2[2 * i]);
            unpack2(x2, x3, o2[2 * i + 1]);
            op[2 * i]     = __floats2half2_rn(x0 * inv, x1 * inv);
            op[2 * i + 1] = __floats2half2_rn(x2 * inv, x3 * inv);
        }
    }
}

// ---------------- layernorm: warp-per-row, 8 rows/CTA, shuffle-only -------
__global__ __launch_bounds__(256)
void ln_kernel(const float* __restrict__ X, const float* __restrict__ g,
               const float* __restrict__ bta,
               float* __restrict__ Y, __half* __restrict__ Y16) {
    int warp = threadIdx.x >> 5;
    int lane = threadIdx.x & 31;
    int row  = blockIdx.x * 8 + warp;

    const float4* x4 = (const float4*)(X + (size_t)row * DEC);
    const float4* g4 = (const float4*)g;
    const float4* b4 = (const float4*)bta;

    float4 v[4];
    float sum = 0.f, sq = 0.f;
    #pragma unroll
    for (int i = 0; i < 4; i++) {
        v[i] = x4[lane + 32 * i];
        sum += (v[i].x + v[i].y) + (v[i].z + v[i].w);
        sq  = fmaf(v[i].x, v[i].x, sq);
        sq  = fmaf(v[i].y, v[i].y, sq);
        sq  = fmaf(v[i].z, v[i].z, sq);
        sq  = fmaf(v[i].w, v[i].w, sq);
    }
    #pragma unroll
    for (int o = 16; o > 0; o >>= 1) {
        sum += __shfl_xor_sync(0xffffffffu, sum, o);
        sq  += __shfl_xor_sync(0xffffffffu, sq,  o);
    }
    float mean = sum * (1.f / DEC);
    float var  = sq * (1.f / DEC) - mean * mean;
    float r = rsqrtf(var + 1e-5f);

    float4*  y4  = (float4*)(Y + (size_t)row * DEC);
    __half2* y16 = (__half2*)(Y16 + (size_t)row * DEC);
    #pragma unroll
    for (int i = 0; i < 4; i++) {
        float4 gv = g4[lane + 32 * i];
        float4 bv = b4[lane + 32 * i];
        float4 o;
        o.x = (v[i].x - mean) * r * gv.x + bv.x;
        o.y = (v[i].y - mean) * r * gv.y + bv.y;
        o.z = (v[i].z - mean) * r * gv.z + bv.z;
        o.w = (v[i].w - mean) * r * gv.w + bv.w;
        y4[lane + 32 * i] = o;
        y16[(lane + 32 * i) * 2]     = __floats2half2_rn(o.x, o.y);
        y16[(lane + 32 * i) * 2 + 1] = __floats2half2_rn(o.z, o.w);
    }
}

// ---------------- host orchestration ----------------
static void launch_gemm(int epi, int outm,
                        const __half* A, const __half* BT, const float* bias,
                        const float* R, float* C, __half* C16,
                        int M, int N, int K) {
    dim3 grid(N / 128, (M + 127) / 128);
    #define GC(E, O) gemm_h<E, O><<<grid, 256>>>(A, BT, bias, R, C, C16, M, N, K)
    if (epi == 0) { if (outm == 0) GC(0,0); else if (outm == 1) GC(0,1); else GC(0,2); }
    else if (epi == 1) { if (outm == 0) GC(1,0); else if (outm == 1) GC(1,1); else GC(1,2); }
    else { if (outm == 0) GC(2,0); else if (outm == 1) GC(2,1); else GC(2,2); }
    #undef GC
}

static void launch_transpose(const float* src, __half* dst, int K, int N,
                             int layers, long long sstride, long long dstride) {
    dim3 grid(N / 32, K / 32, layers);
    transpose_h<<<grid, dim3(32, 8)>>>(src, dst, K, N, sstride, dstride);
}

extern "C" void kernel_launch(void* const* d_in, const int* in_sizes, int n_in,
                              void* d_out, int out_size) {
    const float* x          = (const float*)d_in[0];
    const void*  mask       = d_in[1];
    const float* Wp         = (const float*)d_in[3];
    const float* bp         = (const float*)d_in[4];
    const float* We2d       = (const float*)d_in[5];
    const float* be2d       = (const float*)d_in[6];
    const float* mask_token = (const float*)d_in[7];
    const float* pos        = (const float*)d_in[8];
    const float* Wqkv       = (const float*)d_in[9];
    const float* bqkv       = (const float*)d_in[10];
    const float* Wo         = (const float*)d_in[11];
    const float* bo         = (const float*)d_in[12];
    const float* ln1g       = (const float*)d_in[13];
    const float* ln1b       = (const float*)d_in[14];
    const float* W1         = (const float*)d_in[15];
    const float* b1         = (const float*)d_in[16];
    const float* W2         = (const float*)d_in[17];
    const float* b2         = (const float*)d_in[18];
    const float* ln2g       = (const float*)d_in[19];
    const float* ln2b       = (const float*)d_in[20];
    const float* Wr         = (const float*)d_in[21];
    const float* br         = (const float*)d_in[22];
    float* out = (float*)d_out;

    float  *p_enc, *p_dec, *p_h, *p_tmp;
    __half *p_vp16, *p_enc16, *p_h16, *p_qkv16, *p_attn16, *p_ffn16, *p_wt16;
    cudaGetSymbolAddress((void**)&p_vp16,  g_vp16);
    cudaGetSymbolAddress((void**)&p_enc,   g_enc);
    cudaGetSymbolAddress((void**)&p_enc16, g_enc16);
    cudaGetSymbolAddress((void**)&p_dec,   g_dec);
    cudaGetSymbolAddress((void**)&p_h,     g_h);
    cudaGetSymbolAddress((void**)&p_h16,   g_h16);
    cudaGetSymbolAddress((void**)&p_qkv16, g_qkv16);
    cudaGetSymbolAddress((void**)&p_attn16,g_attn16);
    cudaGetSymbolAddress((void**)&p_ffn16, g_ffn16);
    cudaGetSymbolAddress((void**)&p_tmp,   g_tmp);
    cudaGetSymbolAddress((void**)&p_wt16,  g_wt16);

    // transpose + fp16-convert all weights: W[K][N] -> WT[N][K]
    launch_transpose(Wp,   p_wt16 + OFF_WP,   OUTD, ENC,  1, 0, 0);
    launch_transpose(We2d, p_wt16 + OFF_WE2D, ENC,  DEC,  1, 0, 0);
    launch_transpose(Wqkv, p_wt16 + OFF_WQKV, DEC, 3*DEC, NLAYERS,
                     (long long)DEC * 3 * DEC, (long long)DEC * 3 * DEC);
    launch_transpose(Wo,   p_wt16 + OFF_WO,   DEC,  DEC,  NLAYERS,
                     (long long)DEC * DEC, (long long)DEC * DEC);
    launch_transpose(W1,   p_wt16 + OFF_W1,   DEC,  FFN,  NLAYERS,
                     (long long)DEC * FFN, (long long)DEC * FFN);
    launch_transpose(W2,   p_wt16 + OFF_W2,   FFN,  DEC,  NLAYERS,
                     (long long)FFN * DEC, (long long)FFN * DEC);
    launch_transpose(Wr,   p_wt16 + OFF_WR,   DEC,  OUTD, 1, 0, 0);

    detect_mask_mode<<<1, 32>>>(mask);
    build_indices<<<BATCH, 32>>>(mask);

    {
        int total = TOK_VIS * OUTD;
        gather_patches<<<(total + 255) / 256, 256>>>(x);
    }

    // encoder projection: [3136,3072] @ [3072,768] (f32 output + f16 copy)
    launch_gemm(0, 2, p_vp16, p_wt16 + OFF_WP, bp, nullptr,
                p_enc, p_enc16, TOK_VIS, ENC, OUTD);
    // enc -> dec: [3136,768] @ [768,512]
    launch_gemm(0, 0, p_enc16, p_wt16 + OFF_WE2D, be2d, nullptr,
                p_dec, nullptr, TOK_VIS, DEC, ENC);

    {
        int total = TOK_FULL * DEC;
        assemble<<<(total + 255) / 256, 256>>>(mask_token, pos);
    }

    for (int l = 0; l < NLAYERS; l++) {
        const __half* Wqkv_l = p_wt16 + OFF_WQKV + (size_t)l * DEC * 3 * DEC;
        const float*  bqkv_l = bqkv + (size_t)l * 3 * DEC;
        const __half* Wo_l   = p_wt16 + OFF_WO + (size_t)l * DEC * DEC;
        const float*  bo_l   = bo   + (size_t)l * DEC;
        const __half* W1_l   = p_wt16 + OFF_W1 + (size_t)l * DEC * FFN;
        const float*  b1_l   = b1   + (size_t)l * FFN;
        const __half* W2_l   = p_wt16 + OFF_W2 + (size_t)l * FFN * DEC;
        const float*  b2_l   = b2   + (size_t)l * DEC;

        // QKV: fp16 output only (attention consumes fp16)
        launch_gemm(0, 1, p_h16, Wqkv_l, bqkv_l, nullptr,
                    nullptr, p_qkv16, TOK_FULL, 3 * DEC, DEC);
        attn_kernel<<<BATCH * NHEADS, 224>>>(p_qkv16, p_attn16);
        launch_gemm(2, 0, p_attn16, Wo_l, bo_l, p_h,
                    p_tmp, nullptr, TOK_FULL, DEC, DEC);
        ln_kernel<<<TOK_FULL / 8, 256>>>(p_tmp, ln1g + (size_t)l * DEC,
                                         ln1b + (size_t)l * DEC, p_h, p_h16);

        launch_gemm(1, 1, p_h16, W1_l, b1_l, nullptr,
                    nullptr, p_ffn16, TOK_FULL, FFN, DEC);
        launch_gemm(2, 0, p_ffn16, W2_l, b2_l, p_h,
                    p_tmp, nullptr, TOK_FULL, DEC, FFN);
        ln_kernel<<<TOK_FULL / 8, 256>>>(p_tmp, ln2g + (size_t)l * DEC,
                                         ln2b + (size_t)l * DEC, p_h, p_h16);
    }

    // reconstruction: [12544,512] @ [512,3072]
    launch_gemm(0, 0, p_h16, p_wt16 + OFF_WR, br, nullptr,
                out, nullptr, TOK_FULL, OUTD, DEC);

    const long long recon_elems = (long long)TOK_FULL * OUTD;
    const long long enc_elems   = (long long)TOK_VIS * ENC;
    if ((long long)out_size >= recon_elems + enc_elems) {
        cudaMemcpyAsync(out + recon_elems, p_enc, enc_elems * sizeof(float),
                        cudaMemcpyDeviceToDevice, 0);
    }
}